// round 10
// baseline (speedup 1.0000x reference)
#include <cuda_runtime.h>
#include <cuda_bf16.h>
#include <cstdint>
#include <cfloat>

// Problem constants
constexpr int BATCH     = 4;
constexpr int GXD       = 480;
constexpr int GYD       = 360;
constexpr int CIN       = 64;
constexpr int COUT      = 32;
constexpr int NPTS      = 480000;
constexpr int SEG_PER_B = GXD * GYD;          // 172800
constexpr int NSEG      = BATCH * SEG_PER_B;  // 691200
constexpr int SCAN_BLOCKS = NSEG / 1024;      // 675 (exact)

// Scratch (fully rewritten every call -> graph-replay safe)
__device__ __align__(16) unsigned int g_counts[NSEG];
__device__ __align__(16) unsigned int g_offs[NSEG];     // excl scan, then cursor
__device__ unsigned int g_bsum[SCAN_BLOCKS];
__device__ unsigned int g_bsum_sc[SCAN_BLOCKS];
__device__ __align__(16) int          g_seg[NPTS];
__device__ __align__(16) unsigned int g_order[NPTS];
// Compact pooled rows: occupied voxel v's 64-ch row lives at row index start(v).
__device__ __align__(16) float        g_pooledc[(size_t)NPTS * CIN];  // 123 MB
__device__ unsigned int g_arrive;   // monotonic arrival counter (never reset)

__device__ __forceinline__ unsigned int warp_incl_scan(unsigned int v) {
#pragma unroll
    for (int d = 1; d < 32; d <<= 1) {
        unsigned int n = __shfl_up_sync(0xffffffffu, v, d);
        if ((threadIdx.x & 31) >= d) v += n;
    }
    return v;
}

// ---------------------------------------------------------------------------
// K1: zero per-voxel counters
// ---------------------------------------------------------------------------
__global__ void zero_counts_kernel() {
    unsigned int i = blockIdx.x * blockDim.x + threadIdx.x;
    if (i < (unsigned int)(NSEG / 4))
        reinterpret_cast<uint4*>(g_counts)[i] = make_uint4(0u, 0u, 0u, 0u);
}

// ---------------------------------------------------------------------------
// K2: per-point voxel id + histogram
// ---------------------------------------------------------------------------
__global__ void hist_kernel(const int* __restrict__ ind,
                            const int* __restrict__ bidx) {
    int i = blockIdx.x * blockDim.x + threadIdx.x;
    if (i >= NPTS) return;
    int2 xy = reinterpret_cast<const int2*>(ind)[i];
    int seg = bidx[i] * SEG_PER_B + xy.x * GYD + xy.y;
    g_seg[i] = seg;
    atomicAdd(&g_counts[seg], 1u);
}

// ---------------------------------------------------------------------------
// K3: local exclusive scan of counts; LAST arriving block also scans the 675
// block sums (kills the separate single-block launch).
// ---------------------------------------------------------------------------
__global__ void scan_local_kernel() {
    __shared__ unsigned int sh[32];
    __shared__ int is_last;
    int i = blockIdx.x * 1024 + threadIdx.x;
    unsigned int v = g_counts[i];
    unsigned int incl = warp_incl_scan(v);
    int lane = threadIdx.x & 31, wid = threadIdx.x >> 5;
    if (lane == 31) sh[wid] = incl;
    __syncthreads();
    if (wid == 0) sh[lane] = warp_incl_scan(sh[lane]);
    __syncthreads();
    unsigned int base = wid ? sh[wid - 1] : 0u;
    g_offs[i] = base + incl - v;
    if (threadIdx.x == 1023) g_bsum[blockIdx.x] = base + incl;

    // last-block finalization of the block-sum scan
    __syncthreads();            // order own g_bsum store before fence
    __threadfence();
    if (threadIdx.x == 0)
        is_last = ((atomicAdd(&g_arrive, 1u) % (unsigned)SCAN_BLOCKS)
                   == (unsigned)(SCAN_BLOCKS - 1));
    __syncthreads();
    if (is_last) {
        int t = threadIdx.x;
        unsigned int v2 = (t < SCAN_BLOCKS) ? __ldcg(&g_bsum[t]) : 0u;
        unsigned int incl2 = warp_incl_scan(v2);
        if (lane == 31) sh[wid] = incl2;
        __syncthreads();
        if (wid == 0) sh[lane] = warp_incl_scan(sh[lane]);
        __syncthreads();
        unsigned int b2 = wid ? sh[wid - 1] : 0u;
        if (t < SCAN_BLOCKS) g_bsum_sc[t] = b2 + incl2 - v2;
    }
}

// ---------------------------------------------------------------------------
// K4: place point ids in voxel-sorted order.
//     end(v) = g_bsum_sc[v>>10] + g_offs[v] (post-increment), start = end-cnt
// ---------------------------------------------------------------------------
__global__ void place_kernel() {
    int i = blockIdx.x * blockDim.x + threadIdx.x;
    if (i >= NPTS) return;
    int seg = g_seg[i];
    unsigned int slot = g_bsum_sc[seg >> 10] + atomicAdd(&g_offs[seg], 1u);
    g_order[slot] = (unsigned int)i;
}

// ---------------------------------------------------------------------------
// K5: pooling (high occupancy, no W). 4 threads per voxel, 16 ch each.
// Writes compact pooled row at row index start(v). 1-deep point prefetch.
// ---------------------------------------------------------------------------
__global__ void __launch_bounds__(256)
pool_kernel(const float* __restrict__ fea) {
    int tid = blockIdx.x * blockDim.x + threadIdx.x;
    int v = tid >> 2;
    if (v >= NSEG) return;
    int q = tid & 3;

    unsigned int cnt = g_counts[v];
    if (!cnt) return;
    unsigned int end = g_bsum_sc[v >> 10] + g_offs[v];
    unsigned int st  = end - cnt;

    float4 m0 = make_float4(-FLT_MAX, -FLT_MAX, -FLT_MAX, -FLT_MAX);
    float4 m1 = m0, m2 = m0, m3 = m0;

    unsigned int p = g_order[st];
    for (unsigned int k = 0; k < cnt; ++k) {
        unsigned int pn = (k + 1 < cnt) ? g_order[st + k + 1] : p;  // prefetch
        const float4* f4 = reinterpret_cast<const float4*>(fea + (size_t)p * CIN);
        float4 a = f4[q + 0];
        float4 b = f4[q + 4];
        float4 c = f4[q + 8];
        float4 d = f4[q + 12];
        m0.x = fmaxf(m0.x, a.x); m0.y = fmaxf(m0.y, a.y);
        m0.z = fmaxf(m0.z, a.z); m0.w = fmaxf(m0.w, a.w);
        m1.x = fmaxf(m1.x, b.x); m1.y = fmaxf(m1.y, b.y);
        m1.z = fmaxf(m1.z, b.z); m1.w = fmaxf(m1.w, b.w);
        m2.x = fmaxf(m2.x, c.x); m2.y = fmaxf(m2.y, c.y);
        m2.z = fmaxf(m2.z, c.z); m2.w = fmaxf(m2.w, c.w);
        m3.x = fmaxf(m3.x, d.x); m3.y = fmaxf(m3.y, d.y);
        m3.z = fmaxf(m3.z, d.z); m3.w = fmaxf(m3.w, d.w);
        p = pn;
    }
    float4* dst = reinterpret_cast<float4*>(g_pooledc) + (size_t)st * 16;
    dst[q + 0]  = m0;   // channels 4q..4q+3
    dst[q + 4]  = m1;   // channels 4q+16..
    dst[q + 8]  = m2;   // channels 4q+32..
    dst[q + 12] = m3;   // channels 4q+48..
}

// ---------------------------------------------------------------------------
// K6: GEMV + transposed coalesced write. Block = 64 consecutive voxels.
// Compact rows of a block's occupied voxels are CONTIGUOUS (start(v) is
// monotonic) -> fully coalesced streaming read. W load + GEMV skipped for
// all-empty blocks (>=25% of grid).
// ---------------------------------------------------------------------------
__global__ void __launch_bounds__(256, 2)
gemv_kernel(const float* __restrict__ W,
            const float* __restrict__ bias,
            float* __restrict__ out) {
    __shared__ float sh_pool[64 * 64];   // 16 KB, linear [local_seg][c]
    __shared__ float sh_out[COUT * 65];
    __shared__ unsigned int sh_cnt[64];
    __shared__ unsigned int sh_start[64];

    const int tid  = threadIdx.x;
    const int lane = tid & 31;
    const int wid  = tid >> 5;
    const int s0   = blockIdx.x * 64;

    unsigned int mycnt = 0;
    if (tid < 64) {
        int v = s0 + tid;
        mycnt = g_counts[v];
        unsigned int end = g_bsum_sc[v >> 10] + g_offs[v];
        sh_cnt[tid]   = mycnt;
        sh_start[tid] = end - mycnt;
    }
    int any = __syncthreads_or(tid < 64 && mycnt > 0);

    float wcol[64];
    float bval = 0.0f;
    if (any) {
        // Lane-private W column + bias (L1-resident after first block)
#pragma unroll
        for (int c = 0; c < 64; c++) wcol[c] = W[c * COUT + lane];
        bval = bias[lane];

        // Cooperative streaming load of occupied rows into shared
        const float4* src = reinterpret_cast<const float4*>(g_pooledc);
#pragma unroll
        for (int it = 0; it < 4; it++) {
            int idx = tid + it * 256;          // 0..1023 float4 slots
            int ls  = idx >> 4;
            if (sh_cnt[ls]) {
                float4 f = src[(size_t)sh_start[ls] * 16 + (idx & 15)];
                *reinterpret_cast<float4*>(&sh_pool[idx * 4]) = f;
            }
        }
    }
    __syncthreads();

    // GEMV: warp owns 8 voxels, lane owns one output channel
#pragma unroll
    for (int j = 0; j < 8; j++) {
        int s = wid * 8 + j;
        float r = 0.0f;
        if (sh_cnt[s]) {
            float acc = bval;
            const float* pr = &sh_pool[s * 64];
#pragma unroll
            for (int cs = 0; cs < 64; cs += 4) {
                float4 p = *reinterpret_cast<const float4*>(&pr[cs]);
                acc = fmaf(p.x, wcol[cs + 0], acc);
                acc = fmaf(p.y, wcol[cs + 1], acc);
                acc = fmaf(p.z, wcol[cs + 2], acc);
                acc = fmaf(p.w, wcol[cs + 3], acc);
            }
            r = fmaxf(acc, 0.0f);
        }
        sh_out[lane * 65 + s] = r;
    }
    __syncthreads();

    // Coalesced transposed write (always, incl. empty blocks: zeros)
    const int bb   = s0 / SEG_PER_B;
    const int rem0 = s0 - bb * SEG_PER_B;
    float* ob = out + (size_t)bb * COUT * SEG_PER_B + rem0;
#pragma unroll
    for (int it = 0; it < 8; it++) {
        int idx = tid + it * 256;
        int co = idx >> 6;
        int yy = idx & 63;
        ob[(size_t)co * SEG_PER_B + yy] = sh_out[co * 65 + yy];
    }
}

// ---------------------------------------------------------------------------
extern "C" void kernel_launch(void* const* d_in, const int* in_sizes, int n_in,
                              void* d_out, int out_size) {
    const float* pt_fea    = (const float*)d_in[0];
    const int*   pt_ind    = (const int*)d_in[1];
    const int*   batch_idx = (const int*)d_in[2];
    const float* W_comp    = (const float*)d_in[3];
    const float* b_comp    = (const float*)d_in[4];
    float* out = (float*)d_out;

    zero_counts_kernel<<<(NSEG / 4 + 255) / 256, 256>>>();
    hist_kernel<<<(NPTS + 255) / 256, 256>>>(pt_ind, batch_idx);
    scan_local_kernel<<<SCAN_BLOCKS, 1024>>>();      // includes bsum scan
    place_kernel<<<(NPTS + 255) / 256, 256>>>();
    pool_kernel<<<(NSEG * 4) / 256, 256>>>(pt_fea);
    gemv_kernel<<<NSEG / 64, 256>>>(W_comp, b_comp, out);
}

// round 13
// speedup vs baseline: 1.0561x; 1.0561x over previous
#include <cuda_runtime.h>
#include <cuda_bf16.h>
#include <cstdint>
#include <cfloat>

// Problem constants
constexpr int BATCH     = 4;
constexpr int GXD       = 480;
constexpr int GYD       = 360;
constexpr int CIN       = 64;
constexpr int COUT      = 32;
constexpr int NPTS      = 480000;
constexpr int SEG_PER_B = GXD * GYD;          // 172800
constexpr int NSEG      = BATCH * SEG_PER_B;  // 691200
constexpr int SCAN_BLOCKS = NSEG / 1024;      // 675 (exact)
constexpr int NTILES    = NSEG / 64;          // 10800

// Scratch (fully rewritten every call -> graph-replay safe)
__device__ __align__(16) unsigned int g_counts[NSEG];
__device__ __align__(16) unsigned int g_offs[NSEG];     // excl scan, then cursor
__device__ unsigned int g_bsum[SCAN_BLOCKS];
__device__ unsigned int g_bsum_sc[SCAN_BLOCKS];
__device__ __align__(16) int          g_seg[NPTS];
// Feature rows scattered into voxel-sorted compact order (123 MB)
__device__ __align__(16) float        g_feas[(size_t)NPTS * CIN];
__device__ unsigned int g_arrive;   // monotonic arrival counter (never reset)

__device__ __forceinline__ unsigned int warp_incl_scan(unsigned int v) {
#pragma unroll
    for (int d = 1; d < 32; d <<= 1) {
        unsigned int n = __shfl_up_sync(0xffffffffu, v, d);
        if ((threadIdx.x & 31) >= d) v += n;
    }
    return v;
}

// ---------------------------------------------------------------------------
// K1: zero per-voxel counters
// ---------------------------------------------------------------------------
__global__ void zero_counts_kernel() {
    unsigned int i = blockIdx.x * blockDim.x + threadIdx.x;
    if (i < (unsigned int)(NSEG / 4))
        reinterpret_cast<uint4*>(g_counts)[i] = make_uint4(0u, 0u, 0u, 0u);
}

// ---------------------------------------------------------------------------
// K2: per-point voxel id + histogram
// ---------------------------------------------------------------------------
__global__ void hist_kernel(const int* __restrict__ ind,
                            const int* __restrict__ bidx) {
    int i = blockIdx.x * blockDim.x + threadIdx.x;
    if (i >= NPTS) return;
    int2 xy = reinterpret_cast<const int2*>(ind)[i];
    int seg = bidx[i] * SEG_PER_B + xy.x * GYD + xy.y;
    g_seg[i] = seg;
    atomicAdd(&g_counts[seg], 1u);
}

// ---------------------------------------------------------------------------
// K3: local exclusive scan of counts; LAST arriving block also scans the 675
// block sums (no separate single-block launch).
// ---------------------------------------------------------------------------
__global__ void scan_local_kernel() {
    __shared__ unsigned int sh[32];
    __shared__ int is_last;
    int i = blockIdx.x * 1024 + threadIdx.x;
    unsigned int v = g_counts[i];
    unsigned int incl = warp_incl_scan(v);
    int lane = threadIdx.x & 31, wid = threadIdx.x >> 5;
    if (lane == 31) sh[wid] = incl;
    __syncthreads();
    if (wid == 0) sh[lane] = warp_incl_scan(sh[lane]);
    __syncthreads();
    unsigned int base = wid ? sh[wid - 1] : 0u;
    g_offs[i] = base + incl - v;
    if (threadIdx.x == 1023) g_bsum[blockIdx.x] = base + incl;

    __syncthreads();
    __threadfence();
    if (threadIdx.x == 0)
        is_last = ((atomicAdd(&g_arrive, 1u) % (unsigned)SCAN_BLOCKS)
                   == (unsigned)(SCAN_BLOCKS - 1));
    __syncthreads();
    if (is_last) {
        int t = threadIdx.x;
        unsigned int v2 = (t < SCAN_BLOCKS) ? __ldcg(&g_bsum[t]) : 0u;
        unsigned int incl2 = warp_incl_scan(v2);
        if (lane == 31) sh[wid] = incl2;
        __syncthreads();
        if (wid == 0) sh[lane] = warp_incl_scan(sh[lane]);
        __syncthreads();
        unsigned int b2 = wid ? sh[wid - 1] : 0u;
        if (t < SCAN_BLOCKS) g_bsum_sc[t] = b2 + incl2 - v2;
    }
}

// ---------------------------------------------------------------------------
// K4: scatter-copy feature rows into voxel-sorted compact order.
// 8 threads per point: leader claims the slot, all 8 copy 2 float4 each.
// Reads fully coalesced; writes are contiguous 256B chunks at scattered
// slots (fire-and-forget stores — no latency exposure).
// ---------------------------------------------------------------------------
__global__ void __launch_bounds__(256)
scatter_copy_kernel(const float* __restrict__ fea) {
    int t = blockIdx.x * blockDim.x + threadIdx.x;
    int p = t >> 3;
    int r = t & 7;
    if (p >= NPTS) return;

    unsigned int slot = 0;
    if (r == 0) {
        int seg = g_seg[p];
        slot = g_bsum_sc[seg >> 10] + atomicAdd(&g_offs[seg], 1u);
    }
    slot = __shfl_sync(0xffffffffu, slot, 0, 8);   // broadcast within 8-lane group

    const float4* src = reinterpret_cast<const float4*>(fea + (size_t)p * CIN);
    float4* dst = reinterpret_cast<float4*>(g_feas + (size_t)slot * CIN);
    dst[r]     = src[r];        // bytes [0,128)   across the 8 lanes
    dst[r + 8] = src[r + 8];    // bytes [128,256) across the 8 lanes
}

// ---------------------------------------------------------------------------
// K5: persistent fused max-pool + Linear(64->32)+ReLU + transposed write.
// Grid = 2 blocks/SM; W column loaded into registers ONCE per block, then
// the block loops over tiles of 64 consecutive voxels. Pool reads are
// contiguous compact rows (start(v) monotonic) -> streaming, no indirection.
// ---------------------------------------------------------------------------
__global__ void __launch_bounds__(256, 2)
pool_gemv_kernel(const float* __restrict__ W,
                 const float* __restrict__ bias,
                 float* __restrict__ out) {
    __shared__ float sh_pool[64 * 64];   // 16 KB, [local_seg][c]
    __shared__ float sh_out[COUT * 65];
    __shared__ unsigned int sh_cnt[64];
    __shared__ unsigned int sh_start[64];

    const int tid  = threadIdx.x;
    const int lane = tid & 31;
    const int wid  = tid >> 5;

    // Lane-private W column + bias: loaded once per (persistent) block.
    float wcol[64];
#pragma unroll
    for (int c = 0; c < 64; c++) wcol[c] = W[c * COUT + lane];
    const float bval = bias[lane];

    for (int tile = blockIdx.x; tile < NTILES; tile += gridDim.x) {
        const int s0 = tile * 64;

        if (tid < 64) {
            int v = s0 + tid;
            unsigned int c = g_counts[v];
            unsigned int end = g_bsum_sc[v >> 10] + g_offs[v];  // cursor == end
            sh_cnt[tid]   = c;
            sh_start[tid] = end - c;
        }
        __syncthreads();

        // --- Pooling: 4 threads/voxel, 16 channels each, contiguous rows ---
        {
            const int s = tid >> 2;
            const int q = tid & 3;
            const unsigned int cnt = sh_cnt[s];
            if (cnt) {
                const unsigned int st = sh_start[s];
                float4 m0 = make_float4(-FLT_MAX, -FLT_MAX, -FLT_MAX, -FLT_MAX);
                float4 m1 = m0, m2 = m0, m3 = m0;
                const float4* rows = reinterpret_cast<const float4*>(g_feas)
                                     + (size_t)st * 16;
                for (unsigned int k = 0; k < cnt; ++k, rows += 16) {
                    float4 a = rows[q + 0];
                    float4 b = rows[q + 4];
                    float4 c = rows[q + 8];
                    float4 d = rows[q + 12];
                    m0.x = fmaxf(m0.x, a.x); m0.y = fmaxf(m0.y, a.y);
                    m0.z = fmaxf(m0.z, a.z); m0.w = fmaxf(m0.w, a.w);
                    m1.x = fmaxf(m1.x, b.x); m1.y = fmaxf(m1.y, b.y);
                    m1.z = fmaxf(m1.z, b.z); m1.w = fmaxf(m1.w, b.w);
                    m2.x = fmaxf(m2.x, c.x); m2.y = fmaxf(m2.y, c.y);
                    m2.z = fmaxf(m2.z, c.z); m2.w = fmaxf(m2.w, c.w);
                    m3.x = fmaxf(m3.x, d.x); m3.y = fmaxf(m3.y, d.y);
                    m3.z = fmaxf(m3.z, d.z); m3.w = fmaxf(m3.w, d.w);
                }
                float4* dst = reinterpret_cast<float4*>(&sh_pool[s * 64 + q * 4]);
                dst[0]  = m0;   // ch 4q+0..3
                dst[4]  = m1;   // ch 4q+16..
                dst[8]  = m2;   // ch 4q+32..
                dst[12] = m3;   // ch 4q+48..
            }
        }
        __syncthreads();

        // --- GEMV: warp owns 8 voxels, lane owns one output channel ---
#pragma unroll
        for (int j = 0; j < 8; j++) {
            int s = wid * 8 + j;
            float r = 0.0f;
            if (sh_cnt[s]) {
                float acc = bval;
                const float* pr = &sh_pool[s * 64];
#pragma unroll
                for (int cs = 0; cs < 64; cs += 4) {
                    float4 p = *reinterpret_cast<const float4*>(&pr[cs]);
                    acc = fmaf(p.x, wcol[cs + 0], acc);
                    acc = fmaf(p.y, wcol[cs + 1], acc);
                    acc = fmaf(p.z, wcol[cs + 2], acc);
                    acc = fmaf(p.w, wcol[cs + 3], acc);
                }
                r = fmaxf(acc, 0.0f);
            }
            sh_out[lane * 65 + s] = r;
        }
        __syncthreads();

        // --- Coalesced transposed write ---
        const int bb   = s0 / SEG_PER_B;
        const int rem0 = s0 - bb * SEG_PER_B;
        float* ob = out + (size_t)bb * COUT * SEG_PER_B + rem0;
#pragma unroll
        for (int it = 0; it < 8; it++) {
            int idx = tid + it * 256;
            int co = idx >> 6;
            int yy = idx & 63;
            ob[(size_t)co * SEG_PER_B + yy] = sh_out[co * 65 + yy];
        }
        __syncthreads();   // protect sh_* reuse next tile
    }
}

// ---------------------------------------------------------------------------
extern "C" void kernel_launch(void* const* d_in, const int* in_sizes, int n_in,
                              void* d_out, int out_size) {
    const float* pt_fea    = (const float*)d_in[0];
    const int*   pt_ind    = (const int*)d_in[1];
    const int*   batch_idx = (const int*)d_in[2];
    const float* W_comp    = (const float*)d_in[3];
    const float* b_comp    = (const float*)d_in[4];
    float* out = (float*)d_out;

    zero_counts_kernel<<<(NSEG / 4 + 255) / 256, 256>>>();
    hist_kernel<<<(NPTS + 255) / 256, 256>>>(pt_ind, batch_idx);
    scan_local_kernel<<<SCAN_BLOCKS, 1024>>>();      // includes bsum scan
    scatter_copy_kernel<<<(NPTS * 8) / 256, 256>>>(pt_fea);
    pool_gemv_kernel<<<296, 256>>>(W_comp, b_comp, out);
}

// round 15
// speedup vs baseline: 1.2524x; 1.1859x over previous
#include <cuda_runtime.h>
#include <cuda_bf16.h>
#include <cstdint>
#include <cfloat>

// Problem constants
constexpr int BATCH     = 4;
constexpr int GXD       = 480;
constexpr int GYD       = 360;
constexpr int CIN       = 64;
constexpr int COUT      = 32;
constexpr int NPTS      = 480000;
constexpr int SEG_PER_B = GXD * GYD;          // 172800
constexpr int NSEG      = BATCH * SEG_PER_B;  // 691200
constexpr int SCAN_BLOCKS = NSEG / 1024;      // 675 (exact)
constexpr int NTILES    = NSEG / 64;          // 10800
constexpr int GRID_FUSED = 296;               // 2 blocks/SM

// Scratch (fully rewritten every call -> graph-replay safe)
__device__ __align__(16) unsigned int g_counts[NSEG];
__device__ __align__(16) unsigned int g_offs[NSEG];     // excl scan, then cursor
__device__ unsigned int g_bsum[SCAN_BLOCKS];
__device__ unsigned int g_bsum_sc[SCAN_BLOCKS];
__device__ __align__(16) int          g_seg[NPTS];
__device__ __align__(16) float        g_feas[(size_t)NPTS * CIN];  // sorted rows
__device__ unsigned int g_arrive;   // monotonic arrival counter (never reset)

__device__ __forceinline__ unsigned int warp_incl_scan(unsigned int v) {
#pragma unroll
    for (int d = 1; d < 32; d <<= 1) {
        unsigned int n = __shfl_up_sync(0xffffffffu, v, d);
        if ((threadIdx.x & 31) >= d) v += n;
    }
    return v;
}
__device__ __forceinline__ float4 max4(float4 a, float4 b) {
    return make_float4(fmaxf(a.x, b.x), fmaxf(a.y, b.y),
                       fmaxf(a.z, b.z), fmaxf(a.w, b.w));
}

// ---------------------------------------------------------------------------
__global__ void zero_counts_kernel() {
    unsigned int i = blockIdx.x * blockDim.x + threadIdx.x;
    if (i < (unsigned int)(NSEG / 4))
        reinterpret_cast<uint4*>(g_counts)[i] = make_uint4(0u, 0u, 0u, 0u);
}

// ---------------------------------------------------------------------------
__global__ void hist_kernel(const int* __restrict__ ind,
                            const int* __restrict__ bidx) {
    int i = blockIdx.x * blockDim.x + threadIdx.x;
    if (i >= NPTS) return;
    int2 xy = reinterpret_cast<const int2*>(ind)[i];
    int seg = bidx[i] * SEG_PER_B + xy.x * GYD + xy.y;
    g_seg[i] = seg;
    atomicAdd(&g_counts[seg], 1u);
}

// ---------------------------------------------------------------------------
// Local scan; LAST arriving block scans the 675 block sums.
// ---------------------------------------------------------------------------
__global__ void scan_local_kernel() {
    __shared__ unsigned int sh[32];
    __shared__ int is_last;
    int i = blockIdx.x * 1024 + threadIdx.x;
    unsigned int v = g_counts[i];
    unsigned int incl = warp_incl_scan(v);
    int lane = threadIdx.x & 31, wid = threadIdx.x >> 5;
    if (lane == 31) sh[wid] = incl;
    __syncthreads();
    if (wid == 0) sh[lane] = warp_incl_scan(sh[lane]);
    __syncthreads();
    unsigned int base = wid ? sh[wid - 1] : 0u;
    g_offs[i] = base + incl - v;
    if (threadIdx.x == 1023) g_bsum[blockIdx.x] = base + incl;

    __syncthreads();
    __threadfence();
    if (threadIdx.x == 0)
        is_last = ((atomicAdd(&g_arrive, 1u) % (unsigned)SCAN_BLOCKS)
                   == (unsigned)(SCAN_BLOCKS - 1));
    __syncthreads();
    if (is_last) {
        int t = threadIdx.x;
        unsigned int v2 = (t < SCAN_BLOCKS) ? __ldcg(&g_bsum[t]) : 0u;
        unsigned int incl2 = warp_incl_scan(v2);
        if (lane == 31) sh[wid] = incl2;
        __syncthreads();
        if (wid == 0) sh[lane] = warp_incl_scan(sh[lane]);
        __syncthreads();
        unsigned int b2 = wid ? sh[wid - 1] : 0u;
        if (t < SCAN_BLOCKS) g_bsum_sc[t] = b2 + incl2 - v2;
    }
}

// ---------------------------------------------------------------------------
// Scatter-copy feature rows into voxel-sorted compact order (near roofline).
// ---------------------------------------------------------------------------
__global__ void __launch_bounds__(256)
scatter_copy_kernel(const float* __restrict__ fea) {
    int t = blockIdx.x * blockDim.x + threadIdx.x;
    int p = t >> 3;
    int r = t & 7;
    if (p >= NPTS) return;

    unsigned int slot = 0;
    if (r == 0) {
        int seg = g_seg[p];
        slot = g_bsum_sc[seg >> 10] + atomicAdd(&g_offs[seg], 1u);
    }
    slot = __shfl_sync(0xffffffffu, slot, 0, 8);

    const float4* src = reinterpret_cast<const float4*>(fea + (size_t)p * CIN);
    float4* dst = reinterpret_cast<float4*>(g_feas + (size_t)slot * CIN);
    dst[r]     = src[r];
    dst[r + 8] = src[r + 8];
}

// ---------------------------------------------------------------------------
// Pipelined persistent fused kernel. Double-buffered sh_pool + meta.
// Iteration t: A) issue row prefetch for tile t+g (regs) + meta for t+2g,
//              B) GEMV + output write for tile t,
//              C) combine prefetched rows -> sh_pool[next], store meta.
// ---------------------------------------------------------------------------
__global__ void __launch_bounds__(256, 2)
pool_gemv_kernel(const float* __restrict__ W,
                 const float* __restrict__ bias,
                 float* __restrict__ out) {
    __shared__ float sh_pool[2][64 * 64];     // 32 KB
    __shared__ float sh_out[COUT * 65];
    __shared__ unsigned int sh_cnt[2][64];
    __shared__ unsigned int sh_start[2][64];

    const int tid  = threadIdx.x;
    const int lane = tid & 31;
    const int wid  = tid >> 5;
    const int s    = tid >> 2;     // pooling voxel
    const int q    = tid & 3;      // channel quarter
    const int g    = GRID_FUSED;

    float wcol[64];
#pragma unroll
    for (int c = 0; c < 64; c++) wcol[c] = W[c * COUT + lane];
    const float bval = bias[lane];

    // ---- prologue: meta for tiles b and b+g; blocking pool of tile b ----
    const int t0 = blockIdx.x;
    if (tid < 64) {
        int v = t0 * 64 + tid;
        unsigned int c = g_counts[v];
        unsigned int e = g_bsum_sc[v >> 10] + g_offs[v];
        sh_cnt[0][tid] = c;  sh_start[0][tid] = e - c;
        int t1 = t0 + g;
        if (t1 < NTILES) {
            int v1 = t1 * 64 + tid;
            unsigned int c1 = g_counts[v1];
            unsigned int e1 = g_bsum_sc[v1 >> 10] + g_offs[v1];
            sh_cnt[1][tid] = c1;  sh_start[1][tid] = e1 - c1;
        }
    }
    __syncthreads();
    {   // blocking pool of tile t0 into sh_pool[0]
        unsigned int cnt = sh_cnt[0][s];
        if (cnt) {
            unsigned int st = sh_start[0][s];
            const float4* rows = reinterpret_cast<const float4*>(g_feas)
                                 + (size_t)st * 16;
            float4 m0 = rows[q], m1 = rows[q + 4], m2 = rows[q + 8], m3 = rows[q + 12];
            rows += 16;
            for (unsigned int k = 1; k < cnt; ++k, rows += 16) {
                m0 = max4(m0, rows[q]);     m1 = max4(m1, rows[q + 4]);
                m2 = max4(m2, rows[q + 8]); m3 = max4(m3, rows[q + 12]);
            }
            float4* dst = reinterpret_cast<float4*>(&sh_pool[0][s * 64 + q * 4]);
            dst[0] = m0; dst[4] = m1; dst[8] = m2; dst[12] = m3;
        }
    }
    __syncthreads();

    int buf = 0;
    for (int t = t0; t < NTILES; t += g, buf ^= 1) {
        const int nbuf = buf ^ 1;
        const int tn  = t + g;
        const int tnn = t + 2 * g;

        // ---- Stage A: issue prefetch (rows for tn, meta for tnn) ----
        unsigned int cnt2 = 0, st2 = 0;
        int pc = 0;
        float4 p00, p01, p02, p03, p10, p11, p12, p13;
        if (tn < NTILES) {
            cnt2 = sh_cnt[nbuf][s];
            st2  = sh_start[nbuf][s];
            pc = (cnt2 < 2u) ? (int)cnt2 : 2;
            const float4* r0 = reinterpret_cast<const float4*>(g_feas)
                               + (size_t)st2 * 16;
            if (pc >= 1) { p00 = r0[q]; p01 = r0[q + 4]; p02 = r0[q + 8]; p03 = r0[q + 12]; }
            if (pc >= 2) { const float4* r1 = r0 + 16;
                           p10 = r1[q]; p11 = r1[q + 4]; p12 = r1[q + 8]; p13 = r1[q + 12]; }
        }
        unsigned int mc = 0, ms = 0;
        if (tid < 64 && tnn < NTILES) {
            int v = tnn * 64 + tid;
            mc = g_counts[v];
            unsigned int e = g_bsum_sc[v >> 10] + g_offs[v];
            ms = e - mc;
        }

        // ---- Stage B: GEMV + output write for tile t ----
#pragma unroll
        for (int j = 0; j < 8; j++) {
            int sv = wid * 8 + j;
            float r = 0.0f;
            if (sh_cnt[buf][sv]) {
                float acc = bval;
                const float* pr = &sh_pool[buf][sv * 64];
#pragma unroll
                for (int cs = 0; cs < 64; cs += 4) {
                    float4 p = *reinterpret_cast<const float4*>(&pr[cs]);
                    acc = fmaf(p.x, wcol[cs + 0], acc);
                    acc = fmaf(p.y, wcol[cs + 1], acc);
                    acc = fmaf(p.z, wcol[cs + 2], acc);
                    acc = fmaf(p.w, wcol[cs + 3], acc);
                }
                r = fmaxf(acc, 0.0f);
            }
            sh_out[lane * 65 + sv] = r;
        }
        __syncthreads();
        {
            const int s0   = t * 64;
            const int bb   = s0 / SEG_PER_B;
            const int rem0 = s0 - bb * SEG_PER_B;
            float* ob = out + (size_t)bb * COUT * SEG_PER_B + rem0;
#pragma unroll
            for (int it = 0; it < 8; it++) {
                int idx = tid + it * 256;
                int co = idx >> 6, yy = idx & 63;
                ob[(size_t)co * SEG_PER_B + yy] = sh_out[co * 65 + yy];
            }
        }
        __syncthreads();   // B fully done: meta[buf] + sh_out now reusable

        // ---- Stage C: combine prefetched rows -> sh_pool[nbuf]; meta store ----
        if (tn < NTILES) {
            if (cnt2) {
                float4 m0 = p00, m1 = p01, m2 = p02, m3 = p03;
                if (pc >= 2) {
                    m0 = max4(m0, p10); m1 = max4(m1, p11);
                    m2 = max4(m2, p12); m3 = max4(m3, p13);
                }
                if (cnt2 > 2u) {       // rare tail, blocking
                    const float4* rows = reinterpret_cast<const float4*>(g_feas)
                                         + ((size_t)st2 + 2) * 16;
                    for (unsigned int k = 2; k < cnt2; ++k, rows += 16) {
                        m0 = max4(m0, rows[q]);     m1 = max4(m1, rows[q + 4]);
                        m2 = max4(m2, rows[q + 8]); m3 = max4(m3, rows[q + 12]);
                    }
                }
                float4* dst = reinterpret_cast<float4*>(&sh_pool[nbuf][s * 64 + q * 4]);
                dst[0] = m0; dst[4] = m1; dst[8] = m2; dst[12] = m3;
            }
            if (tid < 64 && tnn < NTILES) {
                sh_cnt[buf][tid] = mc;  sh_start[buf][tid] = ms;
            }
        }
        __syncthreads();
    }
}

// ---------------------------------------------------------------------------
extern "C" void kernel_launch(void* const* d_in, const int* in_sizes, int n_in,
                              void* d_out, int out_size) {
    const float* pt_fea    = (const float*)d_in[0];
    const int*   pt_ind    = (const int*)d_in[1];
    const int*   batch_idx = (const int*)d_in[2];
    const float* W_comp    = (const float*)d_in[3];
    const float* b_comp    = (const float*)d_in[4];
    float* out = (float*)d_out;

    zero_counts_kernel<<<(NSEG / 4 + 255) / 256, 256>>>();
    hist_kernel<<<(NPTS + 255) / 256, 256>>>(pt_ind, batch_idx);
    scan_local_kernel<<<SCAN_BLOCKS, 1024>>>();
    scatter_copy_kernel<<<(NPTS * 8) / 256, 256>>>(pt_fea);
    pool_gemv_kernel<<<GRID_FUSED, 256>>>(W_comp, b_comp, out);
}